// round 15
// baseline (speedup 1.0000x reference)
#include <cuda_runtime.h>
#include <cuda_fp16.h>
#include <cstdint>
#include <math.h>

// ---------------- problem constants (B fixed at 4096 by dataset) ----------
#define NB      4096
#define N_TOK   16
#define C_DIM   512
#define M_POOL  28
#define H_NUM   8
#define HD      64
#define MQ   (NB * N_TOK)    // 65536
#define MP   (NB * M_POOL)   // 114688

// ---------------- global scratch (allocation-free workaround) -------------
__device__ __half g_xh[(size_t)MQ * C_DIM];
__device__ __half g_ph[(size_t)MP * C_DIM];
__device__ __half g_oh[(size_t)MQ * C_DIM];
__device__ __half g_wq[512 * 512];
__device__ __half g_wkv[1024 * 512];
__device__ __half g_wp[512 * 512];
__device__ __half g_Qm[(size_t)MQ * C_DIM];
__device__ __half g_KVm[(size_t)MP * 1024];

// ---------------- helpers --------------------------------------------------
__device__ __forceinline__ uint32_t smem_u32(const void* p) {
    uint32_t a;
    asm("{ .reg .u64 t; cvta.to.shared.u64 t, %1; cvt.u32.u64 %0, t; }"
        : "=r"(a) : "l"(p));
    return a;
}
__device__ __forceinline__ void cp16(uint32_t dst, const void* src) {
    asm volatile("cp.async.cg.shared.global [%0], [%1], 16;"
                 :: "r"(dst), "l"(src) : "memory");
}
__device__ __forceinline__ void ldsm4(uint32_t& r0, uint32_t& r1,
                                      uint32_t& r2, uint32_t& r3, uint32_t addr) {
    asm volatile("ldmatrix.sync.aligned.m8n8.x4.shared.b16 {%0,%1,%2,%3}, [%4];"
                 : "=r"(r0), "=r"(r1), "=r"(r2), "=r"(r3) : "r"(addr));
}
__device__ __forceinline__ void mma16816h(float* c, const uint32_t* a, const uint32_t* b) {
    asm volatile(
        "mma.sync.aligned.m16n8k16.row.col.f32.f16.f16.f32 "
        "{%0,%1,%2,%3},{%4,%5,%6,%7},{%8,%9},{%0,%1,%2,%3};"
        : "+f"(c[0]), "+f"(c[1]), "+f"(c[2]), "+f"(c[3])
        : "r"(a[0]), "r"(a[1]), "r"(a[2]), "r"(a[3]), "r"(b[0]), "r"(b[1]));
}

// ---------------- GEMM tile body (fp16, 128x256 tile, 8 warps) ------------
// 2-stage cp.async, BK=64, one __syncthreads per chunk.
// Warp grid 2x4, warp tile 64x64.
#define BK     64
#define NCHUNK (C_DIM / BK)            // 8
#define SAS    72                      // padded smem row stride (fp16 elems)
#define MATA   (128 * SAS * 2)         // 18432 B: A, one stage
#define MATBB  (256 * SAS * 2)         // 36864 B: B, one stage
#define GSMEM  (2 * (MATA + MATBB))    // 110592 B

template <int HALF_OUT>
__device__ __forceinline__ void gemm_tile_body(
    const __half* __restrict__ Am, const __half* __restrict__ Bm,
    void* __restrict__ Cout, const float* __restrict__ bias,
    int ldC, int m0, int n0, char* smraw)
{
    const uint32_t sbase = smem_u32(smraw);          // A stages at 0, B at 2*MATA
    const uint32_t sB0   = sbase + 2 * MATA;
    const int tid = threadIdx.x, lane = tid & 31, wid = tid >> 5;
    const int wm = wid >> 2, wn = wid & 3;           // 2 x 4 warps, 64x64 tiles

    float acc[4][8][4];
    #pragma unroll
    for (int i = 0; i < 4; i++)
        #pragma unroll
        for (int j = 0; j < 8; j++)
            #pragma unroll
            for (int q = 0; q < 4; q++) acc[i][j][q] = 0.f;

    // one chunk = A 128x64 + B 256x64 fp16 (49KB), 12 cp16 per thread
    auto ldchunk = [&](int kc, int buf) {
        const int k0 = kc * BK;
        #pragma unroll
        for (int t = 0; t < 12; t++) {
            const int idx = tid + t * 256;           // 0..3071
            const int r = idx >> 3, s = idx & 7;
            if (r < 128) {
                const uint32_t doff = (uint32_t)(r * SAS + s * 8) * 2 + buf * MATA;
                cp16(sbase + doff, Am + (size_t)(m0 + r) * 512 + k0 + s * 8);
            } else {
                const int rb = r - 128;
                const uint32_t doff = (uint32_t)(rb * SAS + s * 8) * 2 + buf * MATBB;
                cp16(sB0 + doff, Bm + (size_t)(n0 + rb) * 512 + k0 + s * 8);
            }
        }
        asm volatile("cp.async.commit_group;" ::: "memory");
    };

    ldchunk(0, 0);

    const int a_row = (lane & 7) + ((lane >> 3) & 1) * 8;
    const int a_k8  = ((lane >> 4) & 1) * 8;
    const int b_row = (lane & 7) + ((lane >> 4) & 1) * 8;
    const int b_k8  = ((lane >> 3) & 1) * 8;

    for (int kc = 0; kc < NCHUNK; kc++) {
        const int buf = kc & 1;
        asm volatile("cp.async.wait_group 0;" ::: "memory");
        __syncthreads();
        if (kc + 1 < NCHUNK) ldchunk(kc + 1, buf ^ 1);

        const uint32_t aA = sbase + buf * MATA;
        const uint32_t bB = sB0 + buf * MATBB;

        #pragma unroll
        for (int ks = 0; ks < 4; ks++) {
            const int kcol = ks * 16;
            uint32_t ah[4][4];
            #pragma unroll
            for (int mf = 0; mf < 4; mf++) {
                const uint32_t ro = (uint32_t)((wm * 64 + mf * 16 + a_row) * SAS + kcol + a_k8) * 2;
                ldsm4(ah[mf][0], ah[mf][1], ah[mf][2], ah[mf][3], aA + ro);
            }
            #pragma unroll
            for (int nf2 = 0; nf2 < 4; nf2++) {
                const uint32_t ro = (uint32_t)((wn * 64 + nf2 * 16 + b_row) * SAS + kcol + b_k8) * 2;
                uint32_t b0[2], b1[2];
                uint32_t t0, t1, t2, t3;
                ldsm4(t0, t1, t2, t3, bB + ro);
                b0[0] = t0; b0[1] = t1; b1[0] = t2; b1[1] = t3;
                #pragma unroll
                for (int mf = 0; mf < 4; mf++) {
                    mma16816h(acc[mf][2*nf2],     ah[mf], b0);
                    mma16816h(acc[mf][2*nf2 + 1], ah[mf], b1);
                }
            }
        }
    }

    const int rbase = m0 + wm * 64 + (lane >> 2);
    const int cbase = n0 + wn * 64 + (lane & 3) * 2;
    if (HALF_OUT) {
        __half* Ch = (__half*)Cout;
        #pragma unroll
        for (int mf = 0; mf < 4; mf++)
            #pragma unroll
            for (int nf = 0; nf < 8; nf++) {
                const int r = rbase + mf * 16;
                const int c = cbase + nf * 8;
                *(__half2*)(Ch + (size_t)r * ldC + c) =
                    __floats2half2_rn(acc[mf][nf][0], acc[mf][nf][1]);
                *(__half2*)(Ch + (size_t)(r + 8) * ldC + c) =
                    __floats2half2_rn(acc[mf][nf][2], acc[mf][nf][3]);
            }
    } else {
        float* Cf = (float*)Cout;
        #pragma unroll
        for (int mf = 0; mf < 4; mf++)
            #pragma unroll
            for (int nf = 0; nf < 8; nf++) {
                const int r = rbase + mf * 16;
                const int c = cbase + nf * 8;
                float bx = 0.f, by = 0.f;
                if (bias) { bx = bias[c]; by = bias[c + 1]; }
                *(float2*)(Cf + (size_t)r * ldC + c) =
                    make_float2(acc[mf][nf][0] + bx, acc[mf][nf][1] + by);
                *(float2*)(Cf + (size_t)(r + 8) * ldC + c) =
                    make_float2(acc[mf][nf][2] + bx, acc[mf][nf][3] + by);
            }
    }
}

// ---------------- kernel A: Q-GEMM and KV-GEMM co-scheduled ---------------
// grid (6, 896): x<2 -> Q tile (N=512, 2 tiles), x>=2 -> KV tile (N=1024, 4).
// m-tiles reversed so first CTAs read freshest g_xh/g_ph (L2-hot).
__global__ __launch_bounds__(256, 2)
void gemm_dual()
{
    extern __shared__ char smraw[];
    const int bx = blockIdx.x;
    if (bx < 2) {
        if (blockIdx.y >= MQ / 128) return;
        const int by = (MQ / 128 - 1) - blockIdx.y;
        gemm_tile_body<1>(g_xh, g_wq, g_Qm, nullptr, 512, by * 128, bx * 256, smraw);
    } else {
        const int by = (MP / 128 - 1) - blockIdx.y;
        gemm_tile_body<1>(g_ph, g_wkv, g_KVm, nullptr, 1024, by * 128, (bx - 2) * 256, smraw);
    }
}

// ---------------- kernel B: proj GEMM (fp32 out + bias), reversed m -------
__global__ __launch_bounds__(256, 2)
void gemm_proj(float* __restrict__ out, const float* __restrict__ bias)
{
    extern __shared__ char smraw[];
    const int by = (int)(gridDim.y - 1 - blockIdx.y);
    gemm_tile_body<0>(g_oh, g_wp, out, bias, 512,
                      by * 128, blockIdx.x * 256, smraw);
}

// ---------------- kernel 2: pools + LayerNorm + weight prep (merged) ------
__global__ __launch_bounds__(256)
void ln_prep_kernel(const float* __restrict__ x, const float* __restrict__ gamma,
                    const float* __restrict__ beta,
                    const float* __restrict__ Wq, const float* __restrict__ Wkv,
                    const float* __restrict__ Wproj)
{
    __shared__ float xs[N_TOK * C_DIM];
    const int tid = threadIdx.x;

    if (blockIdx.x >= NB) {
        int idx = (blockIdx.x - NB) * 256 + tid;
        if (idx < 262144) {
            int o = idx; int n = o >> 9, k = o & 511;
            g_wq[o] = __float2half(Wq[k * 512 + n]);
        } else if (idx < 786432) {
            int o = idx - 262144; int n = o >> 9, k = o & 511;
            g_wkv[o] = __float2half(Wkv[k * 1024 + n]);
        } else {
            int o = idx - 786432; int n = o >> 9, k = o & 511;
            g_wp[o] = __float2half(Wproj[k * 512 + n]);
        }
        return;
    }

    const int b = blockIdx.x, wid = tid >> 5, lane = tid & 31;

    const float4* src = (const float4*)(x + (size_t)b * (N_TOK * C_DIM));
    float4* dst = (float4*)xs;
    #pragma unroll 4
    for (int i = tid; i < (N_TOK * C_DIM) / 4; i += 256) dst[i] = src[i];
    __syncthreads();

    const size_t xo = (size_t)b * (N_TOK * C_DIM);
    #pragma unroll 4
    for (int i = tid; i < N_TOK * C_DIM; i += 256)
        g_xh[xo + i] = __float2half(xs[i]);

    const int g1a[8] = {2, 5, 1, 0, 8, 14, 11, 10};
    const int g1b[8] = {3, 6, 4, 7, 9, 15, 12, 13};
    const int g2a[4] = {0, 2, 5, 4};
    const int g2b[4] = {1, 3, 6, 7};

    for (int r = wid; r < M_POOL; r += 8) {
        float vloc[16];
        float s = 0.f, ss = 0.f;
        #pragma unroll
        for (int t = 0; t < 16; t++) {
            int i = lane + t * 32;
            float v;
            if (r < 16)      v = xs[r * C_DIM + i];
            else if (r < 24) { int j = r - 16; v = 0.5f * (xs[g1a[j]*C_DIM + i] + xs[g1b[j]*C_DIM + i]); }
            else             { int j = r - 24; v = 0.5f * (xs[g2a[j]*C_DIM + i] + xs[g2b[j]*C_DIM + i]); }
            vloc[t] = v; s += v; ss += v * v;
        }
        #pragma unroll
        for (int o = 16; o; o >>= 1) {
            s  += __shfl_xor_sync(0xffffffffu, s,  o);
            ss += __shfl_xor_sync(0xffffffffu, ss, o);
        }
        const float mu  = s * (1.f / (float)C_DIM);
        const float var = ss * (1.f / (float)C_DIM) - mu * mu;
        const float inv = rsqrtf(var + 1e-5f);
        const size_t po = ((size_t)b * M_POOL + r) * C_DIM;
        #pragma unroll
        for (int t = 0; t < 16; t++) {
            int i = lane + t * 32;
            g_ph[po + i] = __float2half((vloc[t] - mu) * inv * gamma[i] + beta[i]);
        }
    }
}

// ---------------- kernel 4: attention (frozen; reversed batch order) ------
#define KP2 65   // half2 row stride for k: odd word stride -> conflict-free

__global__ __launch_bounds__(128)
void attn_kernel()
{
    __shared__ __half2 qs2[N_TOK * 64];
    __shared__ __half2 kp2[32 * KP2];
    __shared__ __half  vsh[M_POOL * 128];
    __shared__ alignas(16) float at[2 * N_TOK * M_POOL];

    const int b = NB - 1 - blockIdx.x;
    const int hp = blockIdx.y;
    const int tid = threadIdx.x, wid = tid >> 5, lane = tid & 31;
    const int col0 = hp * 128;

    {
        const __half2* qb = (const __half2*)(g_Qm + (size_t)b * (N_TOK * C_DIM) + col0);
        #pragma unroll
        for (int t = 0; t < 8; t++) {
            const int i = tid + t * 128;
            const int r = i >> 6, c2 = i & 63;
            qs2[r * 64 + c2] = qb[(size_t)r * 256 + c2];
        }
        const __half2* kb = (const __half2*)(g_KVm + (size_t)b * M_POOL * 1024 + col0);
        const __half2* vb = kb + 256;
        __half2* vsh2 = (__half2*)vsh;
        for (int i = tid; i < M_POOL * 64; i += 128) {
            const int r = i >> 6, c2 = i & 63;
            kp2[r * KP2 + c2]  = kb[(size_t)r * 512 + c2];
            vsh2[r * 64 + c2]  = vb[(size_t)r * 512 + c2];
        }
    }
    __syncthreads();

    {
        const int lh = wid >> 1;
        const int nbase = (wid & 1) * 8;
        const int off2 = lh * 32;
        const __half2* krow = kp2 + lane * KP2 + off2;
        #pragma unroll 2
        for (int ni = 0; ni < 8; ni++) {
            const int n = nbase + ni;
            const __half2* qrow = qs2 + n * 64 + off2;
            float s = 0.f;
            #pragma unroll
            for (int d = 0; d < 32; d++) {
                float2 qf = __half22float2(qrow[d]);
                float2 kf = __half22float2(krow[d]);
                s += qf.x * kf.x + qf.y * kf.y;
            }
            s *= 0.125f;
            if (lane >= M_POOL) s = -INFINITY;
            float mx = s;
            #pragma unroll
            for (int o = 16; o; o >>= 1) mx = fmaxf(mx, __shfl_xor_sync(0xffffffffu, mx, o));
            float e = (lane < M_POOL) ? expf(s - mx) : 0.f;
            float ssum = e;
            #pragma unroll
            for (int o = 16; o; o >>= 1) ssum += __shfl_xor_sync(0xffffffffu, ssum, o);
            if (lane < M_POOL) at[(lh * 16 + n) * M_POOL + lane] = e / ssum;
        }
    }
    __syncthreads();

    const int c = tid;
    const int lh = c >> 6;
    float vreg[M_POOL];
    #pragma unroll
    for (int m = 0; m < M_POOL; m++) vreg[m] = __half2float(vsh[m * 128 + c]);

    float acc[N_TOK];
    #pragma unroll
    for (int n = 0; n < N_TOK; n++) {
        const float4* row = (const float4*)(at + (lh * 16 + n) * M_POOL);
        float a = 0.f;
        #pragma unroll
        for (int k4 = 0; k4 < 7; k4++) {
            const float4 w = row[k4];
            a += w.x * vreg[k4 * 4]     + w.y * vreg[k4 * 4 + 1]
               + w.z * vreg[k4 * 4 + 2] + w.w * vreg[k4 * 4 + 3];
        }
        acc[n] = a;
    }
    const size_t oo = (size_t)b * (N_TOK * C_DIM) + col0 + c;
    #pragma unroll
    for (int n = 0; n < N_TOK; n++)
        g_oh[oo + (size_t)n * C_DIM] = __float2half(acc[n]);
}

// ---------------- launch ---------------------------------------------------
extern "C" void kernel_launch(void* const* d_in, const int* in_sizes, int n_in,
                              void* d_out, int out_size)
{
    const float* x     = (const float*)d_in[0];
    const float* Wq    = (const float*)d_in[1];
    const float* Wkv   = (const float*)d_in[2];
    const float* Wproj = (const float*)d_in[3];
    const float* bproj = (const float*)d_in[4];
    const float* gamma = (const float*)d_in[5];
    const float* beta  = (const float*)d_in[6];
    float* out = (float*)d_out;

    const int B = in_sizes[0] / (N_TOK * C_DIM);

    static bool attr_done = false;
    if (!attr_done) {
        cudaFuncSetAttribute(gemm_dual, cudaFuncAttributeMaxDynamicSharedMemorySize, GSMEM);
        cudaFuncSetAttribute(gemm_proj, cudaFuncAttributeMaxDynamicSharedMemorySize, GSMEM);
        attr_done = true;
    }

    ln_prep_kernel<<<B + 4096, 256>>>(x, gamma, beta, Wq, Wkv, Wproj);
    gemm_dual<<<dim3(6, (B * M_POOL) / 128), 256, GSMEM>>>();
    attn_kernel<<<dim3(B, 4), 128>>>();
    gemm_proj<<<dim3(2, (B * N_TOK) / 128), 256, GSMEM>>>(out, bproj);
}

// round 16
// speedup vs baseline: 2.1611x; 2.1611x over previous
#include <cuda_runtime.h>
#include <cuda_fp16.h>
#include <cstdint>
#include <math.h>

// ---------------- problem constants (B fixed at 4096 by dataset) ----------
#define NB      4096
#define N_TOK   16
#define C_DIM   512
#define M_POOL  28
#define H_NUM   8
#define HD      64
#define MQ   (NB * N_TOK)    // 65536
#define MP   (NB * M_POOL)   // 114688

// ---------------- global scratch (allocation-free workaround) -------------
__device__ __half g_xh[(size_t)MQ * C_DIM];
__device__ __half g_ph[(size_t)MP * C_DIM];
__device__ __half g_oh[(size_t)MQ * C_DIM];
__device__ __half g_wq[512 * 512];
__device__ __half g_wkv[1024 * 512];
__device__ __half g_wp[512 * 512];
__device__ __half g_Qm[(size_t)MQ * C_DIM];
__device__ __half g_KVm[(size_t)MP * 1024];

// ---------------- helpers --------------------------------------------------
__device__ __forceinline__ uint32_t smem_u32(const void* p) {
    uint32_t a;
    asm("{ .reg .u64 t; cvta.to.shared.u64 t, %1; cvt.u32.u64 %0, t; }"
        : "=r"(a) : "l"(p));
    return a;
}
__device__ __forceinline__ void cp16(uint32_t dst, const void* src) {
    asm volatile("cp.async.cg.shared.global [%0], [%1], 16;"
                 :: "r"(dst), "l"(src) : "memory");
}
__device__ __forceinline__ void ldsm4(uint32_t& r0, uint32_t& r1,
                                      uint32_t& r2, uint32_t& r3, uint32_t addr) {
    asm volatile("ldmatrix.sync.aligned.m8n8.x4.shared.b16 {%0,%1,%2,%3}, [%4];"
                 : "=r"(r0), "=r"(r1), "=r"(r2), "=r"(r3) : "r"(addr));
}
__device__ __forceinline__ void mma16816h(float* c, const uint32_t* a, const uint32_t* b) {
    asm volatile(
        "mma.sync.aligned.m16n8k16.row.col.f32.f16.f16.f32 "
        "{%0,%1,%2,%3},{%4,%5,%6,%7},{%8,%9},{%0,%1,%2,%3};"
        : "+f"(c[0]), "+f"(c[1]), "+f"(c[2]), "+f"(c[3])
        : "r"(a[0]), "r"(a[1]), "r"(a[2]), "r"(a[3]), "r"(b[0]), "r"(b[1]));
}

// ---------------- GEMM tile body (fp16, 128x256 tile, 8 warps) ------------
// 2-stage cp.async, BK=64, one __syncthreads per chunk.
// Warp grid 2x4, warp tile 64x64. 1 CTA/SM (255-reg cap, no spills).
#define BK     64
#define NCHUNK (C_DIM / BK)            // 8
#define SAS    72                      // padded smem row stride (fp16 elems)
#define MATA   (128 * SAS * 2)         // 18432 B: A, one stage
#define MATBB  (256 * SAS * 2)         // 36864 B: B, one stage
#define GSMEM  (2 * (MATA + MATBB))    // 110592 B

template <int HALF_OUT>
__device__ __forceinline__ void gemm_tile_body(
    const __half* __restrict__ Am, const __half* __restrict__ Bm,
    void* __restrict__ Cout, const float* __restrict__ bias,
    int ldC, int m0, int n0, char* smraw)
{
    const uint32_t sbase = smem_u32(smraw);          // A stages at 0, B at 2*MATA
    const uint32_t sB0   = sbase + 2 * MATA;
    const int tid = threadIdx.x, lane = tid & 31, wid = tid >> 5;
    const int wm = wid >> 2, wn = wid & 3;           // 2 x 4 warps, 64x64 tiles

    float acc[4][8][4];
    #pragma unroll
    for (int i = 0; i < 4; i++)
        #pragma unroll
        for (int j = 0; j < 8; j++)
            #pragma unroll
            for (int q = 0; q < 4; q++) acc[i][j][q] = 0.f;

    // one chunk = A 128x64 + B 256x64 fp16 (49KB), 12 cp16 per thread
    auto ldchunk = [&](int kc, int buf) {
        const int k0 = kc * BK;
        #pragma unroll
        for (int t = 0; t < 12; t++) {
            const int idx = tid + t * 256;           // 0..3071
            const int r = idx >> 3, s = idx & 7;
            if (r < 128) {
                const uint32_t doff = (uint32_t)(r * SAS + s * 8) * 2 + buf * MATA;
                cp16(sbase + doff, Am + (size_t)(m0 + r) * 512 + k0 + s * 8);
            } else {
                const int rb = r - 128;
                const uint32_t doff = (uint32_t)(rb * SAS + s * 8) * 2 + buf * MATBB;
                cp16(sB0 + doff, Bm + (size_t)(n0 + rb) * 512 + k0 + s * 8);
            }
        }
        asm volatile("cp.async.commit_group;" ::: "memory");
    };

    ldchunk(0, 0);

    const int a_row = (lane & 7) + ((lane >> 3) & 1) * 8;
    const int a_k8  = ((lane >> 4) & 1) * 8;
    const int b_row = (lane & 7) + ((lane >> 4) & 1) * 8;
    const int b_k8  = ((lane >> 3) & 1) * 8;

    for (int kc = 0; kc < NCHUNK; kc++) {
        const int buf = kc & 1;
        asm volatile("cp.async.wait_group 0;" ::: "memory");
        __syncthreads();
        if (kc + 1 < NCHUNK) ldchunk(kc + 1, buf ^ 1);

        const uint32_t aA = sbase + buf * MATA;
        const uint32_t bB = sB0 + buf * MATBB;

        #pragma unroll
        for (int ks = 0; ks < 4; ks++) {
            const int kcol = ks * 16;
            uint32_t ah[4][4];
            #pragma unroll
            for (int mf = 0; mf < 4; mf++) {
                const uint32_t ro = (uint32_t)((wm * 64 + mf * 16 + a_row) * SAS + kcol + a_k8) * 2;
                ldsm4(ah[mf][0], ah[mf][1], ah[mf][2], ah[mf][3], aA + ro);
            }
            #pragma unroll
            for (int nf2 = 0; nf2 < 4; nf2++) {
                const uint32_t ro = (uint32_t)((wn * 64 + nf2 * 16 + b_row) * SAS + kcol + b_k8) * 2;
                uint32_t b0[2], b1[2];
                uint32_t t0, t1, t2, t3;
                ldsm4(t0, t1, t2, t3, bB + ro);
                b0[0] = t0; b0[1] = t1; b1[0] = t2; b1[1] = t3;
                #pragma unroll
                for (int mf = 0; mf < 4; mf++) {
                    mma16816h(acc[mf][2*nf2],     ah[mf], b0);
                    mma16816h(acc[mf][2*nf2 + 1], ah[mf], b1);
                }
            }
        }
    }

    const int rbase = m0 + wm * 64 + (lane >> 2);
    const int cbase = n0 + wn * 64 + (lane & 3) * 2;
    if (HALF_OUT) {
        __half* Ch = (__half*)Cout;
        #pragma unroll
        for (int mf = 0; mf < 4; mf++)
            #pragma unroll
            for (int nf = 0; nf < 8; nf++) {
                const int r = rbase + mf * 16;
                const int c = cbase + nf * 8;
                *(__half2*)(Ch + (size_t)r * ldC + c) =
                    __floats2half2_rn(acc[mf][nf][0], acc[mf][nf][1]);
                *(__half2*)(Ch + (size_t)(r + 8) * ldC + c) =
                    __floats2half2_rn(acc[mf][nf][2], acc[mf][nf][3]);
            }
    } else {
        float* Cf = (float*)Cout;
        #pragma unroll
        for (int mf = 0; mf < 4; mf++)
            #pragma unroll
            for (int nf = 0; nf < 8; nf++) {
                const int r = rbase + mf * 16;
                const int c = cbase + nf * 8;
                float bx = 0.f, by = 0.f;
                if (bias) { bx = bias[c]; by = bias[c + 1]; }
                *(float2*)(Cf + (size_t)r * ldC + c) =
                    make_float2(acc[mf][nf][0] + bx, acc[mf][nf][1] + by);
                *(float2*)(Cf + (size_t)(r + 8) * ldC + c) =
                    make_float2(acc[mf][nf][2] + bx, acc[mf][nf][3] + by);
            }
    }
}

// ---------------- kernel A: Q-GEMM and KV-GEMM co-scheduled ---------------
// grid (6, 896): x<2 -> Q tile (N=512, 2 tiles), x>=2 -> KV tile (N=1024, 4).
// m-tiles reversed so first CTAs read freshest g_xh/g_ph (L2-hot).
__global__ __launch_bounds__(256, 1)
void gemm_dual()
{
    extern __shared__ char smraw[];
    const int bx = blockIdx.x;
    if (bx < 2) {
        if (blockIdx.y >= MQ / 128) return;
        const int by = (MQ / 128 - 1) - blockIdx.y;
        gemm_tile_body<1>(g_xh, g_wq, g_Qm, nullptr, 512, by * 128, bx * 256, smraw);
    } else {
        const int by = (MP / 128 - 1) - blockIdx.y;
        gemm_tile_body<1>(g_ph, g_wkv, g_KVm, nullptr, 1024, by * 128, (bx - 2) * 256, smraw);
    }
}

// ---------------- kernel B: proj GEMM (fp32 out + bias), reversed m -------
__global__ __launch_bounds__(256, 1)
void gemm_proj(float* __restrict__ out, const float* __restrict__ bias)
{
    extern __shared__ char smraw[];
    const int by = (int)(gridDim.y - 1 - blockIdx.y);
    gemm_tile_body<0>(g_oh, g_wp, out, bias, 512,
                      by * 128, blockIdx.x * 256, smraw);
}

// ---------------- kernel 2: pools + LayerNorm + weight prep (merged) ------
__global__ __launch_bounds__(256)
void ln_prep_kernel(const float* __restrict__ x, const float* __restrict__ gamma,
                    const float* __restrict__ beta,
                    const float* __restrict__ Wq, const float* __restrict__ Wkv,
                    const float* __restrict__ Wproj)
{
    __shared__ float xs[N_TOK * C_DIM];
    const int tid = threadIdx.x;

    if (blockIdx.x >= NB) {
        int idx = (blockIdx.x - NB) * 256 + tid;
        if (idx < 262144) {
            int o = idx; int n = o >> 9, k = o & 511;
            g_wq[o] = __float2half(Wq[k * 512 + n]);
        } else if (idx < 786432) {
            int o = idx - 262144; int n = o >> 9, k = o & 511;
            g_wkv[o] = __float2half(Wkv[k * 1024 + n]);
        } else {
            int o = idx - 786432; int n = o >> 9, k = o & 511;
            g_wp[o] = __float2half(Wproj[k * 512 + n]);
        }
        return;
    }

    const int b = blockIdx.x, wid = tid >> 5, lane = tid & 31;

    const float4* src = (const float4*)(x + (size_t)b * (N_TOK * C_DIM));
    float4* dst = (float4*)xs;
    #pragma unroll 4
    for (int i = tid; i < (N_TOK * C_DIM) / 4; i += 256) dst[i] = src[i];
    __syncthreads();

    const size_t xo = (size_t)b * (N_TOK * C_DIM);
    #pragma unroll 4
    for (int i = tid; i < N_TOK * C_DIM; i += 256)
        g_xh[xo + i] = __float2half(xs[i]);

    const int g1a[8] = {2, 5, 1, 0, 8, 14, 11, 10};
    const int g1b[8] = {3, 6, 4, 7, 9, 15, 12, 13};
    const int g2a[4] = {0, 2, 5, 4};
    const int g2b[4] = {1, 3, 6, 7};

    for (int r = wid; r < M_POOL; r += 8) {
        float vloc[16];
        float s = 0.f, ss = 0.f;
        #pragma unroll
        for (int t = 0; t < 16; t++) {
            int i = lane + t * 32;
            float v;
            if (r < 16)      v = xs[r * C_DIM + i];
            else if (r < 24) { int j = r - 16; v = 0.5f * (xs[g1a[j]*C_DIM + i] + xs[g1b[j]*C_DIM + i]); }
            else             { int j = r - 24; v = 0.5f * (xs[g2a[j]*C_DIM + i] + xs[g2b[j]*C_DIM + i]); }
            vloc[t] = v; s += v; ss += v * v;
        }
        #pragma unroll
        for (int o = 16; o; o >>= 1) {
            s  += __shfl_xor_sync(0xffffffffu, s,  o);
            ss += __shfl_xor_sync(0xffffffffu, ss, o);
        }
        const float mu  = s * (1.f / (float)C_DIM);
        const float var = ss * (1.f / (float)C_DIM) - mu * mu;
        const float inv = rsqrtf(var + 1e-5f);
        const size_t po = ((size_t)b * M_POOL + r) * C_DIM;
        #pragma unroll
        for (int t = 0; t < 16; t++) {
            int i = lane + t * 32;
            g_ph[po + i] = __float2half((vloc[t] - mu) * inv * gamma[i] + beta[i]);
        }
    }
}

// ---------------- kernel 4: attention (frozen; reversed batch order) ------
#define KP2 65   // half2 row stride for k: odd word stride -> conflict-free

__global__ __launch_bounds__(128)
void attn_kernel()
{
    __shared__ __half2 qs2[N_TOK * 64];
    __shared__ __half2 kp2[32 * KP2];
    __shared__ __half  vsh[M_POOL * 128];
    __shared__ alignas(16) float at[2 * N_TOK * M_POOL];

    const int b = NB - 1 - blockIdx.x;
    const int hp = blockIdx.y;
    const int tid = threadIdx.x, wid = tid >> 5, lane = tid & 31;
    const int col0 = hp * 128;

    {
        const __half2* qb = (const __half2*)(g_Qm + (size_t)b * (N_TOK * C_DIM) + col0);
        #pragma unroll
        for (int t = 0; t < 8; t++) {
            const int i = tid + t * 128;
            const int r = i >> 6, c2 = i & 63;
            qs2[r * 64 + c2] = qb[(size_t)r * 256 + c2];
        }
        const __half2* kb = (const __half2*)(g_KVm + (size_t)b * M_POOL * 1024 + col0);
        const __half2* vb = kb + 256;
        __half2* vsh2 = (__half2*)vsh;
        for (int i = tid; i < M_POOL * 64; i += 128) {
            const int r = i >> 6, c2 = i & 63;
            kp2[r * KP2 + c2]  = kb[(size_t)r * 512 + c2];
            vsh2[r * 64 + c2]  = vb[(size_t)r * 512 + c2];
        }
    }
    __syncthreads();

    {
        const int lh = wid >> 1;
        const int nbase = (wid & 1) * 8;
        const int off2 = lh * 32;
        const __half2* krow = kp2 + lane * KP2 + off2;
        #pragma unroll 2
        for (int ni = 0; ni < 8; ni++) {
            const int n = nbase + ni;
            const __half2* qrow = qs2 + n * 64 + off2;
            float s = 0.f;
            #pragma unroll
            for (int d = 0; d < 32; d++) {
                float2 qf = __half22float2(qrow[d]);
                float2 kf = __half22float2(krow[d]);
                s += qf.x * kf.x + qf.y * kf.y;
            }
            s *= 0.125f;
            if (lane >= M_POOL) s = -INFINITY;
            float mx = s;
            #pragma unroll
            for (int o = 16; o; o >>= 1) mx = fmaxf(mx, __shfl_xor_sync(0xffffffffu, mx, o));
            float e = (lane < M_POOL) ? expf(s - mx) : 0.f;
            float ssum = e;
            #pragma unroll
            for (int o = 16; o; o >>= 1) ssum += __shfl_xor_sync(0xffffffffu, ssum, o);
            if (lane < M_POOL) at[(lh * 16 + n) * M_POOL + lane] = e / ssum;
        }
    }
    __syncthreads();

    const int c = tid;
    const int lh = c >> 6;
    float vreg[M_POOL];
    #pragma unroll
    for (int m = 0; m < M_POOL; m++) vreg[m] = __half2float(vsh[m * 128 + c]);

    float acc[N_TOK];
    #pragma unroll
    for (int n = 0; n < N_TOK; n++) {
        const float4* row = (const float4*)(at + (lh * 16 + n) * M_POOL);
        float a = 0.f;
        #pragma unroll
        for (int k4 = 0; k4 < 7; k4++) {
            const float4 w = row[k4];
            a += w.x * vreg[k4 * 4]     + w.y * vreg[k4 * 4 + 1]
               + w.z * vreg[k4 * 4 + 2] + w.w * vreg[k4 * 4 + 3];
        }
        acc[n] = a;
    }
    const size_t oo = (size_t)b * (N_TOK * C_DIM) + col0 + c;
    #pragma unroll
    for (int n = 0; n < N_TOK; n++)
        g_oh[oo + (size_t)n * C_DIM] = __float2half(acc[n]);
}

// ---------------- launch ---------------------------------------------------
extern "C" void kernel_launch(void* const* d_in, const int* in_sizes, int n_in,
                              void* d_out, int out_size)
{
    const float* x     = (const float*)d_in[0];
    const float* Wq    = (const float*)d_in[1];
    const float* Wkv   = (const float*)d_in[2];
    const float* Wproj = (const float*)d_in[3];
    const float* bproj = (const float*)d_in[4];
    const float* gamma = (const float*)d_in[5];
    const float* beta  = (const float*)d_in[6];
    float* out = (float*)d_out;

    const int B = in_sizes[0] / (N_TOK * C_DIM);

    static bool attr_done = false;
    if (!attr_done) {
        cudaFuncSetAttribute(gemm_dual, cudaFuncAttributeMaxDynamicSharedMemorySize, GSMEM);
        cudaFuncSetAttribute(gemm_proj, cudaFuncAttributeMaxDynamicSharedMemorySize, GSMEM);
        attr_done = true;
    }

    ln_prep_kernel<<<B + 4096, 256>>>(x, gamma, beta, Wq, Wkv, Wproj);
    gemm_dual<<<dim3(6, (B * M_POOL) / 128), 256, GSMEM>>>();
    attn_kernel<<<dim3(B, 4), 128>>>();
    gemm_proj<<<dim3(2, (B * N_TOK) / 128), 256, GSMEM>>>(out, bproj);
}

// round 17
// speedup vs baseline: 2.4050x; 1.1128x over previous
#include <cuda_runtime.h>
#include <cuda_fp16.h>
#include <cstdint>
#include <math.h>

// ---------------- problem constants (B fixed at 4096 by dataset) ----------
#define NB      4096
#define N_TOK   16
#define C_DIM   512
#define M_POOL  28
#define H_NUM   8
#define HD      64
#define MQ   (NB * N_TOK)    // 65536
#define MP   (NB * M_POOL)   // 114688
#define NWTILE 256           // 64x64 transpose tiles over all 3 weight mats

// ---------------- global scratch (allocation-free workaround) -------------
__device__ __half g_xh[(size_t)MQ * C_DIM];
__device__ __half g_ph[(size_t)MP * C_DIM];
__device__ __half g_oh[(size_t)MQ * C_DIM];
__device__ __half g_wq[512 * 512];
__device__ __half g_wkv[1024 * 512];
__device__ __half g_wp[512 * 512];
__device__ __half g_Qm[(size_t)MQ * C_DIM];
__device__ __half g_KVm[(size_t)MP * 1024];

// ---------------- helpers --------------------------------------------------
__device__ __forceinline__ uint32_t smem_u32(const void* p) {
    uint32_t a;
    asm("{ .reg .u64 t; cvta.to.shared.u64 t, %1; cvt.u32.u64 %0, t; }"
        : "=r"(a) : "l"(p));
    return a;
}
__device__ __forceinline__ void cp16(uint32_t dst, const void* src) {
    asm volatile("cp.async.cg.shared.global [%0], [%1], 16;"
                 :: "r"(dst), "l"(src) : "memory");
}
__device__ __forceinline__ void ldsm4(uint32_t& r0, uint32_t& r1,
                                      uint32_t& r2, uint32_t& r3, uint32_t addr) {
    asm volatile("ldmatrix.sync.aligned.m8n8.x4.shared.b16 {%0,%1,%2,%3}, [%4];"
                 : "=r"(r0), "=r"(r1), "=r"(r2), "=r"(r3) : "r"(addr));
}
__device__ __forceinline__ void mma16816h(float* c, const uint32_t* a, const uint32_t* b) {
    asm volatile(
        "mma.sync.aligned.m16n8k16.row.col.f32.f16.f16.f32 "
        "{%0,%1,%2,%3},{%4,%5,%6,%7},{%8,%9},{%0,%1,%2,%3};"
        : "+f"(c[0]), "+f"(c[1]), "+f"(c[2]), "+f"(c[3])
        : "r"(a[0]), "r"(a[1]), "r"(a[2]), "r"(a[3]), "r"(b[0]), "r"(b[1]));
}

// ---------------- GEMM tile body (R14 config: 128x128, 4 warps, 3-stage) --
#define BK     64
#define NCHUNK (C_DIM / BK)          // 8
#define SAS    72                    // padded smem row stride (fp16 elems)
#define MATB   (128 * SAS * 2)       // 18432 B: one matrix, one buffer
#define GSMEM  (6 * MATB)            // 2 matrices x 3 stages = 110592 B

template <int HALF_OUT>
__device__ __forceinline__ void gemm_tile_body(
    const __half* __restrict__ Am, const __half* __restrict__ Bm,
    void* __restrict__ Cout, const float* __restrict__ bias,
    int ldC, int m0, int n0, char* smraw)
{
    const uint32_t sbase = smem_u32(smraw);
    const int tid = threadIdx.x, lane = tid & 31, wid = tid >> 5;
    const int wm = wid >> 1, wn = wid & 1;

    float acc[4][8][4];
    #pragma unroll
    for (int i = 0; i < 4; i++)
        #pragma unroll
        for (int j = 0; j < 8; j++)
            #pragma unroll
            for (int q = 0; q < 4; q++) acc[i][j][q] = 0.f;

    auto ldchunk = [&](int kc, int buf) {
        const int k0 = kc * BK;
        #pragma unroll
        for (int t = 0; t < 8; t++) {
            const int idx = tid + t * 128;
            const int r = idx >> 3, s = idx & 7;
            const uint32_t doff = (uint32_t)(r * SAS + s * 8) * 2 + buf * MATB;
            const size_t ao = (size_t)(m0 + r) * 512 + k0 + s * 8;
            const size_t bo = (size_t)(n0 + r) * 512 + k0 + s * 8;
            cp16(sbase + 0 * 3 * MATB + doff, Am + ao);
            cp16(sbase + 1 * 3 * MATB + doff, Bm + bo);
        }
        asm volatile("cp.async.commit_group;" ::: "memory");
    };

    ldchunk(0, 0);
    ldchunk(1, 1);

    const int a_row = (lane & 7) + ((lane >> 3) & 1) * 8;
    const int a_k8  = ((lane >> 4) & 1) * 8;
    const int b_row = (lane & 7) + ((lane >> 4) & 1) * 8;
    const int b_k8  = ((lane >> 3) & 1) * 8;

    #pragma unroll
    for (int kc = 0; kc < NCHUNK; kc++) {
        const int buf = kc % 3;
        asm volatile("cp.async.wait_group 1;" ::: "memory");
        __syncthreads();
        if (kc + 2 < NCHUNK) ldchunk(kc + 2, (kc + 2) % 3);

        const uint32_t aA = sbase + 0 * 3 * MATB + buf * MATB;
        const uint32_t bB = sbase + 1 * 3 * MATB + buf * MATB;

        #pragma unroll
        for (int ks = 0; ks < 4; ks++) {
            const int kcol = ks * 16;
            uint32_t ah[4][4];
            #pragma unroll
            for (int mf = 0; mf < 4; mf++) {
                const uint32_t ro = (uint32_t)((wm * 64 + mf * 16 + a_row) * SAS + kcol + a_k8) * 2;
                ldsm4(ah[mf][0], ah[mf][1], ah[mf][2], ah[mf][3], aA + ro);
            }
            #pragma unroll
            for (int nf2 = 0; nf2 < 4; nf2++) {
                const uint32_t ro = (uint32_t)((wn * 64 + nf2 * 16 + b_row) * SAS + kcol + b_k8) * 2;
                uint32_t b0[2], b1[2];
                uint32_t t0, t1, t2, t3;
                ldsm4(t0, t1, t2, t3, bB + ro);
                b0[0] = t0; b0[1] = t1; b1[0] = t2; b1[1] = t3;
                #pragma unroll
                for (int mf = 0; mf < 4; mf++) {
                    mma16816h(acc[mf][2*nf2],     ah[mf], b0);
                    mma16816h(acc[mf][2*nf2 + 1], ah[mf], b1);
                }
            }
        }
    }

    const int rbase = m0 + wm * 64 + (lane >> 2);
    const int cbase = n0 + wn * 64 + (lane & 3) * 2;
    if (HALF_OUT) {
        __half* Ch = (__half*)Cout;
        #pragma unroll
        for (int mf = 0; mf < 4; mf++)
            #pragma unroll
            for (int nf = 0; nf < 8; nf++) {
                const int r = rbase + mf * 16;
                const int c = cbase + nf * 8;
                *(__half2*)(Ch + (size_t)r * ldC + c) =
                    __floats2half2_rn(acc[mf][nf][0], acc[mf][nf][1]);
                *(__half2*)(Ch + (size_t)(r + 8) * ldC + c) =
                    __floats2half2_rn(acc[mf][nf][2], acc[mf][nf][3]);
            }
    } else {
        float* Cf = (float*)Cout;
        #pragma unroll
        for (int mf = 0; mf < 4; mf++)
            #pragma unroll
            for (int nf = 0; nf < 8; nf++) {
                const int r = rbase + mf * 16;
                const int c = cbase + nf * 8;
                float bx = 0.f, by = 0.f;
                if (bias) { bx = bias[c]; by = bias[c + 1]; }
                *(float2*)(Cf + (size_t)r * ldC + c) =
                    make_float2(acc[mf][nf][0] + bx, acc[mf][nf][1] + by);
                *(float2*)(Cf + (size_t)(r + 8) * ldC + c) =
                    make_float2(acc[mf][nf][2] + bx, acc[mf][nf][3] + by);
            }
    }
}

// ---------------- kernel A: Q-GEMM and KV-GEMM co-scheduled ---------------
__global__ __launch_bounds__(128, 2)
void gemm_dual()
{
    extern __shared__ char smraw[];
    const int bx = blockIdx.x;
    if (bx < 4) {
        if (blockIdx.y >= MQ / 128) return;
        const int by = (MQ / 128 - 1) - blockIdx.y;
        gemm_tile_body<1>(g_xh, g_wq, g_Qm, nullptr, 512, by * 128, bx * 128, smraw);
    } else {
        const int by = (MP / 128 - 1) - blockIdx.y;
        gemm_tile_body<1>(g_ph, g_wkv, g_KVm, nullptr, 1024, by * 128, (bx - 4) * 128, smraw);
    }
}

// ---------------- kernel B: proj GEMM (fp32 out + bias), reversed m -------
__global__ __launch_bounds__(128, 2)
void gemm_proj(float* __restrict__ out, const float* __restrict__ bias)
{
    extern __shared__ char smraw[];
    const int by = (int)(gridDim.y - 1 - blockIdx.y);
    gemm_tile_body<0>(g_oh, g_wp, out, bias, 512,
                      by * 128, blockIdx.x * 128, smraw);
}

// ---------------- kernel 2: LN (vectorized) + tiled weight transpose ------
__global__ __launch_bounds__(256)
void ln_prep_kernel(const float* __restrict__ x, const float* __restrict__ gamma,
                    const float* __restrict__ beta,
                    const float* __restrict__ Wq, const float* __restrict__ Wkv,
                    const float* __restrict__ Wproj)
{
    __shared__ float xs[N_TOK * C_DIM];    // 32KB; also holds 64x65 transpose tile
    const int tid = threadIdx.x;

    if (blockIdx.x >= NB) {
        // ---- 64x64 smem-tiled weight transpose (coalesced both ways) ----
        const int wb = blockIdx.x - NB;     // 0..255
        const float* W; __half* Wd; int N, m;
        if (wb < 64)        { W = Wq;    Wd = g_wq;  N = 512;  m = wb; }
        else if (wb < 192)  { W = Wkv;   Wd = g_wkv; N = 1024; m = wb - 64; }
        else                { W = Wproj; Wd = g_wp;  N = 512;  m = wb - 192; }
        const int tiles_n = N >> 6;
        const int n0 = (m % tiles_n) << 6;
        const int k0 = (m / tiles_n) << 6;
        // load: rows k, cols n (coalesced over n)
        #pragma unroll
        for (int t = 0; t < 16; t++) {
            const int idx = tid + t * 256;         // 0..4095
            const int r = idx >> 6, c = idx & 63;
            xs[r * 65 + c] = W[(size_t)(k0 + r) * N + n0 + c];
        }
        __syncthreads();
        // store: rows n, cols k (coalesced over k; smem stride-65 reads)
        #pragma unroll
        for (int t = 0; t < 16; t++) {
            const int idx = tid + t * 256;
            const int r2 = idx >> 6, c2 = idx & 63;
            Wd[(size_t)(n0 + r2) * 512 + k0 + c2] = __float2half(xs[c2 * 65 + r2]);
        }
        return;
    }

    const int b = blockIdx.x, wid = tid >> 5, lane = tid & 31;

    const float4* src = (const float4*)(x + (size_t)b * (N_TOK * C_DIM));
    float4* dst = (float4*)xs;
    #pragma unroll 4
    for (int i = tid; i < (N_TOK * C_DIM) / 4; i += 256) dst[i] = src[i];
    __syncthreads();

    // x -> fp16 (half2 stores)
    {
        __half2* xh2 = (__half2*)(g_xh + (size_t)b * (N_TOK * C_DIM));
        const float2* xs2 = (const float2*)xs;
        #pragma unroll 4
        for (int i = tid; i < (N_TOK * C_DIM) / 2; i += 256) {
            float2 f = xs2[i];
            xh2[i] = __floats2half2_rn(f.x, f.y);
        }
    }

    const int g1a[8] = {2, 5, 1, 0, 8, 14, 11, 10};
    const int g1b[8] = {3, 6, 4, 7, 9, 15, 12, 13};
    const int g2a[4] = {0, 2, 5, 4};
    const int g2b[4] = {1, 3, 6, 7};

    for (int r = wid; r < M_POOL; r += 8) {
        float2 vloc[8];
        float s = 0.f, ss = 0.f;
        #pragma unroll
        for (int t = 0; t < 8; t++) {
            const int c2 = lane + t * 32;           // float2 column 0..255
            float2 v;
            if (r < 16) {
                v = ((const float2*)(xs + r * C_DIM))[c2];
            } else if (r < 24) {
                int j = r - 16;
                float2 a = ((const float2*)(xs + g1a[j] * C_DIM))[c2];
                float2 bb = ((const float2*)(xs + g1b[j] * C_DIM))[c2];
                v = make_float2(0.5f * (a.x + bb.x), 0.5f * (a.y + bb.y));
            } else {
                int j = r - 24;
                float2 a = ((const float2*)(xs + g2a[j] * C_DIM))[c2];
                float2 bb = ((const float2*)(xs + g2b[j] * C_DIM))[c2];
                v = make_float2(0.5f * (a.x + bb.x), 0.5f * (a.y + bb.y));
            }
            vloc[t] = v;
            s += v.x + v.y;
            ss += v.x * v.x + v.y * v.y;
        }
        #pragma unroll
        for (int o = 16; o; o >>= 1) {
            s  += __shfl_xor_sync(0xffffffffu, s,  o);
            ss += __shfl_xor_sync(0xffffffffu, ss, o);
        }
        const float mu  = s * (1.f / (float)C_DIM);
        const float var = ss * (1.f / (float)C_DIM) - mu * mu;
        const float inv = rsqrtf(var + 1e-5f);
        __half2* ph2 = (__half2*)(g_ph + ((size_t)b * M_POOL + r) * C_DIM);
        const float2* g2 = (const float2*)gamma;
        const float2* b2 = (const float2*)beta;
        #pragma unroll
        for (int t = 0; t < 8; t++) {
            const int c2 = lane + t * 32;
            float2 gm = g2[c2], bt = b2[c2];
            float ox = (vloc[t].x - mu) * inv * gm.x + bt.x;
            float oy = (vloc[t].y - mu) * inv * gm.y + bt.y;
            ph2[c2] = __floats2half2_rn(ox, oy);
        }
    }
}

// ---------------- kernel 4: attention (frozen; reversed batch order) ------
#define KP2 65   // half2 row stride for k: odd word stride -> conflict-free

__global__ __launch_bounds__(128)
void attn_kernel()
{
    __shared__ __half2 qs2[N_TOK * 64];
    __shared__ __half2 kp2[32 * KP2];
    __shared__ __half  vsh[M_POOL * 128];
    __shared__ alignas(16) float at[2 * N_TOK * M_POOL];

    const int b = NB - 1 - blockIdx.x;
    const int hp = blockIdx.y;
    const int tid = threadIdx.x, wid = tid >> 5, lane = tid & 31;
    const int col0 = hp * 128;

    {
        const __half2* qb = (const __half2*)(g_Qm + (size_t)b * (N_TOK * C_DIM) + col0);
        #pragma unroll
        for (int t = 0; t < 8; t++) {
            const int i = tid + t * 128;
            const int r = i >> 6, c2 = i & 63;
            qs2[r * 64 + c2] = qb[(size_t)r * 256 + c2];
        }
        const __half2* kb = (const __half2*)(g_KVm + (size_t)b * M_POOL * 1024 + col0);
        const __half2* vb = kb + 256;
        __half2* vsh2 = (__half2*)vsh;
        for (int i = tid; i < M_POOL * 64; i += 128) {
            const int r = i >> 6, c2 = i & 63;
            kp2[r * KP2 + c2]  = kb[(size_t)r * 512 + c2];
            vsh2[r * 64 + c2]  = vb[(size_t)r * 512 + c2];
        }
    }
    __syncthreads();

    {
        const int lh = wid >> 1;
        const int nbase = (wid & 1) * 8;
        const int off2 = lh * 32;
        const __half2* krow = kp2 + lane * KP2 + off2;
        #pragma unroll 2
        for (int ni = 0; ni < 8; ni++) {
            const int n = nbase + ni;
            const __half2* qrow = qs2 + n * 64 + off2;
            float s = 0.f;
            #pragma unroll
            for (int d = 0; d < 32; d++) {
                float2 qf = __half22float2(qrow[d]);
                float2 kf = __half22float2(krow[d]);
                s += qf.x * kf.x + qf.y * kf.y;
            }
            s *= 0.125f;
            if (lane >= M_POOL) s = -INFINITY;
            float mx = s;
            #pragma unroll
            for (int o = 16; o; o >>= 1) mx = fmaxf(mx, __shfl_xor_sync(0xffffffffu, mx, o));
            float e = (lane < M_POOL) ? expf(s - mx) : 0.f;
            float ssum = e;
            #pragma unroll
            for (int o = 16; o; o >>= 1) ssum += __shfl_xor_sync(0xffffffffu, ssum, o);
            if (lane < M_POOL) at[(lh * 16 + n) * M_POOL + lane] = e / ssum;
        }
    }
    __syncthreads();

    const int c = tid;
    const int lh = c >> 6;
    float vreg[M_POOL];
    #pragma unroll
    for (int m = 0; m < M_POOL; m++) vreg[m] = __half2float(vsh[m * 128 + c]);

    float acc[N_TOK];
    #pragma unroll
    for (int n = 0; n < N_TOK; n++) {
        const float4* row = (const float4*)(at + (lh * 16 + n) * M_POOL);
        float a = 0.f;
        #pragma unroll
        for (int k4 = 0; k4 < 7; k4++) {
            const float4 w = row[k4];
            a += w.x * vreg[k4 * 4]     + w.y * vreg[k4 * 4 + 1]
               + w.z * vreg[k4 * 4 + 2] + w.w * vreg[k4 * 4 + 3];
        }
        acc[n] = a;
    }
    const size_t oo = (size_t)b * (N_TOK * C_DIM) + col0 + c;
    #pragma unroll
    for (int n = 0; n < N_TOK; n++)
        g_oh[oo + (size_t)n * C_DIM] = __float2half(acc[n]);
}

// ---------------- launch ---------------------------------------------------
extern "C" void kernel_launch(void* const* d_in, const int* in_sizes, int n_in,
                              void* d_out, int out_size)
{
    const float* x     = (const float*)d_in[0];
    const float* Wq    = (const float*)d_in[1];
    const float* Wkv   = (const float*)d_in[2];
    const float* Wproj = (const float*)d_in[3];
    const float* bproj = (const float*)d_in[4];
    const float* gamma = (const float*)d_in[5];
    const float* beta  = (const float*)d_in[6];
    float* out = (float*)d_out;

    const int B = in_sizes[0] / (N_TOK * C_DIM);

    static bool attr_done = false;
    if (!attr_done) {
        cudaFuncSetAttribute(gemm_dual, cudaFuncAttributeMaxDynamicSharedMemorySize, GSMEM);
        cudaFuncSetAttribute(gemm_proj, cudaFuncAttributeMaxDynamicSharedMemorySize, GSMEM);
        attr_done = true;
    }

    ln_prep_kernel<<<B + NWTILE, 256>>>(x, gamma, beta, Wq, Wkv, Wproj);
    gemm_dual<<<dim3(12, (B * M_POOL) / 128), 128, GSMEM>>>();
    attn_kernel<<<dim3(B, 4), 128>>>();
    gemm_proj<<<dim3(4, (B * N_TOK) / 128), 128, GSMEM>>>(out, bproj);
}